// round 3
// baseline (speedup 1.0000x reference)
#include <cuda_runtime.h>
#include <cstdint>

#define TSTEPS 2048
#define BATCH  128
#define HID    256
#define INDIM  82
#define CLU    8
#define BPC    8
#define NTHR   1024
#define HSTRIDE 264            // floats per batch row (two 132-float halves)
#define HHALF   132
#define HBUFLEN (BPC*HSTRIDE)  // 2112 floats per phase
#define GSTRIDE 18             // floats per gate row: [b*2 + kh]

// ---- shared memory layout (bytes) ----
#define OFF_W4    0
#define SZ_W4     (64*128*16)             // W_hh slice float4 [k4][row] = 131072
#define OFF_WIH   (OFF_W4 + SZ_W4)        // 131072 ; transposed [col][row]
#define SZ_WIH    (INDIM*128*4)           // 41984
#define OFF_BIAS  (OFF_WIH + SZ_WIH)      // 173056
#define SZ_BIAS   (512)
#define OFF_HBUF  (OFF_BIAS + SZ_BIAS)    // 173568 ; [2][8][HSTRIDE]
#define SZ_HBUF   (2*HBUFLEN*4)           // 16896
#define OFF_GATES (OFF_HBUF + SZ_HBUF)    // 190464 ; [2][128][GSTRIDE]
#define SZ_GATES  (2*128*GSTRIDE*4)       // 18432
#define OFF_INP   (OFF_GATES + SZ_GATES)  // 208896
#define SZ_INP    (2*128)
#define OFF_MBAR  (OFF_INP + SZ_INP)      // 209152
#define SMEM_TOTAL (OFF_MBAR + 16)        // 209168

#define EXCH_BYTES (CLU*BPC*32*4)         // 8192 bytes per phase per CTA

typedef unsigned long long ull;

__device__ __forceinline__ ull fma2(ull a, ull b, ull c){
  ull d; asm("fma.rn.f32x2 %0, %1, %2, %3;" : "=l"(d) : "l"(a),"l"(b),"l"(c)); return d;
}
__device__ __forceinline__ float lo32(ull v){ return __uint_as_float((unsigned)(v & 0xffffffffull)); }
__device__ __forceinline__ float hi32(ull v){ return __uint_as_float((unsigned)(v >> 32)); }
__device__ __forceinline__ float sigf(float x){ return __fdividef(1.f, 1.f + __expf(-x)); }
__device__ __forceinline__ float tanhf_(float x){ return __fdividef(2.f, 1.f + __expf(-2.f*x)) - 1.f; }
__device__ __forceinline__ uint32_t s2u(const void* p){
  uint32_t a;
  asm("{.reg .u64 t; cvta.to.shared.u64 t, %1; cvt.u32.u64 %0, t;}" : "=r"(a) : "l"(p));
  return a;
}
__device__ __forceinline__ void mbar_init(uint32_t m, int cnt){
  asm volatile("mbarrier.init.shared.b64 [%0], %1;" :: "r"(m), "r"(cnt) : "memory");
}
__device__ __forceinline__ void mbar_arm(uint32_t m, int bytes){
  asm volatile("mbarrier.arrive.expect_tx.shared.b64 _, [%0], %1;" :: "r"(m), "r"(bytes) : "memory");
}
__device__ __forceinline__ void mbar_wait(uint32_t m, uint32_t parity){
  asm volatile(
    "{\n\t.reg .pred P;\n\t"
    "WLP%=:\n\t"
    "mbarrier.try_wait.parity.acquire.cluster.shared::cta.b64 P, [%0], %1, 0x989680;\n\t"
    "@!P bra WLP%=;\n\t}"
    :: "r"(m), "r"(parity) : "memory");
}
__device__ __forceinline__ void st_async_f32(uint32_t raddr, float v, uint32_t rmbar){
  asm volatile("st.async.shared::cluster.mbarrier::complete_tx::bytes.b32 [%0], %1, [%2];"
               :: "r"(raddr), "r"(__float_as_uint(v)), "r"(rmbar) : "memory");
}
__device__ __forceinline__ uint32_t mapa_u32(uint32_t la, int rank){
  uint32_t ra;
  asm("mapa.shared::cluster.u32 %0, %1, %2;" : "=r"(ra) : "r"(la), "r"(rank));
  return ra;
}

extern __shared__ char smem[];

__global__ void __cluster_dims__(CLU,1,1) __launch_bounds__(NTHR,1)
lstm_scan_kernel(const int* __restrict__ X, const float* __restrict__ H0,
                 const int* __restrict__ A, const float* __restrict__ R,
                 const float* __restrict__ Dn,
                 const float* __restrict__ Wih, const float* __restrict__ Whh,
                 const float* __restrict__ bih, const float* __restrict__ bhh,
                 float* __restrict__ out)
{
  const int tid = threadIdx.x;
  const int uc  = blockIdx.x & (CLU-1);   // cluster rank: which 32 hidden units
  const int bg  = blockIdx.x / CLU;       // batch group of 8
  const int gb0 = bg * BPC;

  float4* W4s    = (float4*)(smem + OFF_W4);
  float*  WihT   = (float*)(smem + OFF_WIH);   // [col][row]
  float*  biasS  = (float*)(smem + OFF_BIAS);
  float*  hbuf   = (float*)(smem + OFF_HBUF);
  float*  gatesS = (float*)(smem + OFF_GATES);

  const uint32_t sb = s2u(smem);

  // ---- one-time staging ----
  // local row lr in [0,128): gate = lr/32, unit = uc*32 + lr%32
  for (int i = tid; i < 64*128; i += NTHR){
    int k4 = i >> 7, lr = i & 127;
    int gr = ((lr >> 5) << 8) + uc*32 + (lr & 31);
    W4s[(k4 << 7) + lr] = ((const float4*)Whh)[gr*64 + k4];
  }
  for (int i = tid; i < 128*INDIM; i += NTHR){
    int lr = i >> 7, c0 = i & 127;          // i = c0*128 + lr? use: lr = i&127, c0 = i>>7
    // (recompute properly below)
    (void)lr; (void)c0;
  }
  for (int i = tid; i < INDIM*128; i += NTHR){
    int c0 = i >> 7, lr = i & 127;
    int gr = ((lr >> 5) << 8) + uc*32 + (lr & 31);
    WihT[c0*128 + lr] = Wih[gr*INDIM + c0];
  }
  for (int i = tid; i < 128; i += NTHR){
    int gr = ((i >> 5) << 8) + uc*32 + (i & 31);
    biasS[i] = bih[gr] + bhh[gr];
  }
  // initial h for our 8 batches -> buffer 0 ([b][kh*132 + k&127])
  for (int i = tid; i < BPC*HID; i += NTHR){
    int b = i >> 8, k = i & 255;
    hbuf[b*HSTRIDE + (k >> 7)*HHALF + (k & 127)] = H0[(gb0 + b)*(2*HID) + k];
  }

  if (tid == 0){
    mbar_init(sb + OFF_MBAR,     1);
    mbar_init(sb + OFF_MBAR + 8, 1);
    mbar_arm (sb + OFF_MBAR,     EXCH_BYTES);
    mbar_arm (sb + OFF_MBAR + 8, EXCH_BYTES);
  }
  __syncthreads();
  asm volatile("barrier.cluster.arrive.aligned;" ::: "memory");
  asm volatile("barrier.cluster.wait.aligned;"   ::: "memory");

  // GEMM mapping: thread = (row r, batch-pair bp, k-half kh)
  const int r  = tid >> 3;
  const int bp = (tid >> 1) & 3;
  const int kh = tid & 1;

  // epilogue identity (threads 0..255): one (batch, unit); warp == one batch
  const int eb = tid >> 5, eu = tid & 31;
  const int ug = uc*32 + eu;
  const int gbb = gb0 + (eb & 7);
  float c = (tid < 256) ? H0[gbb*(2*HID) + HID + ug] : 0.f;
  float h_last = 0.f;
  const unsigned exoff = 4u*(unsigned)((eb & 7)*HSTRIDE + (ug >> 7)*HHALF + (ug & 127));

  uint32_t ph0 = 0, ph1 = 0;

  for (int t = 0; t < TSTEPS; ++t){
    const int cb = t & 1;
    const int nb = cb ^ 1;

    if (t > 0){
      uint32_t m = sb + OFF_MBAR + cb*8;
      uint32_t par = cb ? ph1 : ph0;
      mbar_wait(m, par);
      if (cb) ph1 ^= 1; else ph0 ^= 1;
      if (tid == 0) mbar_arm(m, EXCH_BYTES);
    }

    // prefetch this step's scalar inputs into buffer cb
    if (tid < 32){
      int b = tid & 7, wch = tid >> 3;
      long idx = (long)(gb0 + b)*TSTEPS + t;
      char* inp = smem + OFF_INP + cb*128;
      if      (wch == 0) ((int*)inp)[b]        = X[idx];
      else if (wch == 1) ((int*)inp)[8 + b]    = A[idx];
      else if (wch == 2) ((float*)inp)[16 + b] = R[idx];
      else               ((float*)inp)[24 + b] = Dn[idx];
    }

    // ---- recurrent GEMM (k-split): partial[row][b][kh] = sum_{k in half} W*h ----
    {
      const ulonglong2* hp0 = (const ulonglong2*)(hbuf + cb*HBUFLEN + bp*HSTRIDE + kh*HHALF);
      const ulonglong2* hp1 = hp0 + (4*HSTRIDE)/4;   // batch bp+4: +1056 floats = +66 u2
      const ulonglong2* wp  = (const ulonglong2*)W4s + (kh << 5)*128 + r;
      ull a0 = 0, a1 = 0;
      #pragma unroll 8
      for (int k4 = 0; k4 < 32; ++k4){
        ulonglong2 wv = wp[0];        // 8 distinct addrs/warp, 4-way multicast
        ulonglong2 h0 = hp0[k4];      // 8 distinct (bp,kh), conflict-free banks
        ulonglong2 h1 = hp1[k4];
        wp += 128;
        a0 = fma2(wv.x, h0.x, a0); a0 = fma2(wv.y, h0.y, a0);
        a1 = fma2(wv.x, h1.x, a1); a1 = fma2(wv.y, h1.y, a1);
      }
      float* gG = gatesS + cb*(128*GSTRIDE);
      gG[r*GSTRIDE + bp*2       + kh] = lo32(a0) + hi32(a0);
      gG[r*GSTRIDE + (bp+4)*2   + kh] = lo32(a1) + hi32(a1);
    }

    __syncthreads();

    // ---- epilogue on threads 0..255 (warp == batch; lanes share xi/ai) ----
    if (tid < 256){
      const char* inp = smem + OFF_INP + cb*128;
      int   xi = ((const int*)inp)[eb];
      int   ai = ((const int*)inp)[8 + eb];
      float rv = ((const float*)inp)[16 + eb];
      float dv = ((const float*)inp)[24 + eb];
      const float* gG = gatesS + cb*(128*GSTRIDE);

      float gate[4];
      #pragma unroll
      for (int g4 = 0; g4 < 4; ++g4){
        int lr = g4*32 + eu;
        float2 pr = *(const float2*)(gG + lr*GSTRIDE + eb*2);
        float xp = WihT[xi*128 + lr] + WihT[(64+ai)*128 + lr]
                 + WihT[80*128 + lr]*rv + WihT[81*128 + lr]*dv + biasS[lr];
        gate[g4] = pr.x + pr.y + xp;
      }
      float I = sigf(gate[0]);
      float F = sigf(gate[1]);
      float G = tanhf_(gate[2]);
      float O = sigf(gate[3]);
      c = F*c + I*G;
      float hv = O * tanhf_(c);
      h_last = hv;

      // broadcast h (for step t+1) to all 8 CTAs' buffer nb
      if (t < TSTEPS-1){
        uint32_t la = sb + OFF_HBUF + (unsigned)(nb*HBUFLEN*4) + exoff;
        uint32_t lm = sb + OFF_MBAR + nb*8;
        #pragma unroll
        for (int p = 0; p < CLU; ++p){
          st_async_f32(mapa_u32(la, p), hv, mapa_u32(lm, p));
        }
      }

      // features[b][t][u]
      out[((size_t)gbb*TSTEPS + t)*HID + ug] = hv;
    }
  }

  if (tid < 256){
    size_t fo = (size_t)BATCH*TSTEPS*HID;
    out[fo + (size_t)gbb*(2*HID) + ug]       = h_last;
    out[fo + (size_t)gbb*(2*HID) + HID + ug] = c;
  }

  asm volatile("barrier.cluster.arrive.aligned;" ::: "memory");
  asm volatile("barrier.cluster.wait.aligned;"   ::: "memory");
}

extern "C" void kernel_launch(void* const* d_in, const int* in_sizes, int n_in,
                              void* d_out, int out_size)
{
  const int*   X   = (const int*)  d_in[0];
  const float* H0  = (const float*)d_in[1];
  const int*   A   = (const int*)  d_in[2];
  const float* R   = (const float*)d_in[3];
  const float* Dn  = (const float*)d_in[4];
  const float* Wih = (const float*)d_in[5];
  const float* Whh = (const float*)d_in[6];
  const float* bih = (const float*)d_in[7];
  const float* bhh = (const float*)d_in[8];
  float* out = (float*)d_out;

  cudaFuncSetAttribute(lstm_scan_kernel,
                       cudaFuncAttributeMaxDynamicSharedMemorySize, SMEM_TOTAL);
  lstm_scan_kernel<<<BATCH, NTHR, SMEM_TOTAL>>>(X, H0, A, R, Dn, Wih, Whh, bih, bhh, out);
}

// round 5
// speedup vs baseline: 2.9877x; 2.9877x over previous
#include <cuda_runtime.h>
#include <cstdint>

#define TSTEPS 2048
#define BATCH  128
#define HID    256
#define INDIM  82
#define CLU    8
#define BPC    8
#define NTHR   512

// ---- shared memory layout (bytes) ----
#define OFF_WIH   0                        // transposed [col][row] : 82*128 floats
#define SZ_WIH    (INDIM*128*4)            // 41984
#define OFF_BIAS  (OFF_WIH + SZ_WIH)       // 41984
#define SZ_BIAS   (512)
#define OFF_HBUF  (OFF_BIAS + SZ_BIAS)     // 42496 ; [2][8][256] floats
#define SZ_HBUF   (2*BPC*HID*4)            // 16384
#define OFF_PART  (OFF_HBUF + SZ_HBUF)     // 58880 ; [2][kc8][b8][128] floats
#define SZ_PART   (2*8*8*128*4)            // 65536
#define OFF_INP   (OFF_PART + SZ_PART)     // 124416 ; [2] x 128B
#define SZ_INP    (2*128)
#define OFF_MBAR  (OFF_INP + SZ_INP)       // 124672
#define SMEM_TOTAL (OFF_MBAR + 16)         // 124688

#define EXCH_BYTES (CLU*BPC*32*4)          // 8192 B arriving per phase per CTA

typedef unsigned long long ull;

__device__ __forceinline__ ull fma2(ull a, ull b, ull c){
  ull d; asm("fma.rn.f32x2 %0, %1, %2, %3;" : "=l"(d) : "l"(a),"l"(b),"l"(c)); return d;
}
__device__ __forceinline__ float lo32(ull v){ return __uint_as_float((unsigned)(v & 0xffffffffull)); }
__device__ __forceinline__ float hi32(ull v){ return __uint_as_float((unsigned)(v >> 32)); }
__device__ __forceinline__ float sigf(float x){ return __fdividef(1.f, 1.f + __expf(-x)); }
__device__ __forceinline__ float tanhf_(float x){ return __fdividef(2.f, 1.f + __expf(-2.f*x)) - 1.f; }
__device__ __forceinline__ uint32_t s2u(const void* p){
  uint32_t a;
  asm("{.reg .u64 t; cvta.to.shared.u64 t, %1; cvt.u32.u64 %0, t;}" : "=r"(a) : "l"(p));
  return a;
}
__device__ __forceinline__ void mbar_init(uint32_t m, int cnt){
  asm volatile("mbarrier.init.shared.b64 [%0], %1;" :: "r"(m), "r"(cnt) : "memory");
}
__device__ __forceinline__ void mbar_arm(uint32_t m, int bytes){
  asm volatile("mbarrier.arrive.expect_tx.shared.b64 _, [%0], %1;" :: "r"(m), "r"(bytes) : "memory");
}
__device__ __forceinline__ void mbar_wait(uint32_t m, uint32_t parity){
  asm volatile(
    "{\n\t.reg .pred P;\n\t"
    "WLP%=:\n\t"
    "mbarrier.try_wait.parity.acquire.cluster.shared::cta.b64 P, [%0], %1, 0x989680;\n\t"
    "@!P bra WLP%=;\n\t}"
    :: "r"(m), "r"(parity) : "memory");
}
__device__ __forceinline__ void st_async_f32(uint32_t raddr, float v, uint32_t rmbar){
  asm volatile("st.async.shared::cluster.mbarrier::complete_tx::bytes.b32 [%0], %1, [%2];"
               :: "r"(raddr), "r"(__float_as_uint(v)), "r"(rmbar) : "memory");
}
__device__ __forceinline__ uint32_t mapa_u32(uint32_t la, int rank){
  uint32_t ra;
  asm("mapa.shared::cluster.u32 %0, %1, %2;" : "=r"(ra) : "r"(la), "r"(rank));
  return ra;
}

extern __shared__ char smem[];

__global__ void __cluster_dims__(CLU,1,1) __launch_bounds__(NTHR,1)
lstm_scan_kernel(const int* __restrict__ X, const float* __restrict__ H0,
                 const int* __restrict__ A, const float* __restrict__ R,
                 const float* __restrict__ Dn,
                 const float* __restrict__ Wih, const float* __restrict__ Whh,
                 const float* __restrict__ bih, const float* __restrict__ bhh,
                 float* __restrict__ out)
{
  const int tid = threadIdx.x;
  const int uc  = blockIdx.x & (CLU-1);   // cluster rank: which 32 hidden units
  const int bg  = blockIdx.x / CLU;       // batch group of 8
  const int gb0 = bg * BPC;

  float* WihT  = (float*)(smem + OFF_WIH);
  float* biasS = (float*)(smem + OFF_BIAS);
  float* hbuf  = (float*)(smem + OFF_HBUF);
  float* partS = (float*)(smem + OFF_PART);

  const uint32_t sb = s2u(smem);

  // ---- GEMM identity: thread = (row-pair rp, k-chunk kc) ----
  const int rp = tid & 63;        // local row pair: rows 2rp, 2rp+1
  const int kc = tid >> 6;        // k-chunk of 32: k in [kc*32, kc*32+32)
  const int lr0 = rp*2, lr1 = lr0 + 1;
  const int gr0 = ((lr0 >> 5) << 8) + uc*32 + (lr0 & 31);
  const int gr1 = ((lr1 >> 5) << 8) + uc*32 + (lr1 & 31);

  // ---- load W_hh slice into registers (weight-stationary) ----
  // row = 256 floats = 64 ulonglong2 (16B each)
  ull w0[16], w1[16];
  {
    const ulonglong2* Wg = (const ulonglong2*)Whh;
    #pragma unroll
    for (int j = 0; j < 8; ++j){
      ulonglong2 u = Wg[gr0*64 + kc*8 + j];
      w0[2*j] = u.x; w0[2*j+1] = u.y;
      ulonglong2 v = Wg[gr1*64 + kc*8 + j];
      w1[2*j] = v.x; w1[2*j+1] = v.y;
    }
  }

  // ---- one-time smem staging ----
  for (int i = tid; i < INDIM*128; i += NTHR){
    int c0 = i >> 7, lr = i & 127;
    int gr = ((lr >> 5) << 8) + uc*32 + (lr & 31);
    WihT[c0*128 + lr] = Wih[gr*INDIM + c0];
  }
  for (int i = tid; i < 128; i += NTHR){
    int gr = ((i >> 5) << 8) + uc*32 + (i & 31);
    biasS[i] = bih[gr] + bhh[gr];
  }
  for (int i = tid; i < BPC*HID; i += NTHR){
    int b = i >> 8, k = i & 255;
    hbuf[b*HID + k] = H0[(gb0 + b)*(2*HID) + k];
  }

  if (tid == 0){
    mbar_init(sb + OFF_MBAR,     1);
    mbar_init(sb + OFF_MBAR + 8, 1);
    mbar_arm (sb + OFF_MBAR,     EXCH_BYTES);
    mbar_arm (sb + OFF_MBAR + 8, EXCH_BYTES);
  }
  __syncthreads();
  asm volatile("barrier.cluster.arrive.aligned;" ::: "memory");
  asm volatile("barrier.cluster.wait.aligned;"   ::: "memory");

  // ---- epilogue identity (threads 0..255): one (batch, unit); warp == batch ----
  const int eb = tid >> 5, eu = tid & 31;
  const int ug = uc*32 + eu;
  const int gbb = gb0 + (eb & 7);
  float c = (tid < 256) ? H0[gbb*(2*HID) + HID + ug] : 0.f;
  float h_last = 0.f;
  // precomputed remote bases for exchange
  uint32_t ra[CLU];
  #pragma unroll
  for (int p = 0; p < CLU; ++p) ra[p] = mapa_u32(sb, p);
  const unsigned hoff0 = (unsigned)(OFF_HBUF) + 4u*(unsigned)((eb & 7)*HID + ug);

  uint32_t ph0 = 0, ph1 = 0;

  for (int t = 0; t < TSTEPS; ++t){
    const int cb = t & 1;
    const int nb = cb ^ 1;

    if (t > 0){
      uint32_t m = sb + OFF_MBAR + cb*8;
      uint32_t par = cb ? ph1 : ph0;
      mbar_wait(m, par);
      if (cb) ph1 ^= 1; else ph0 ^= 1;
      if (tid == 0) mbar_arm(m, EXCH_BYTES);
    }

    // prefetch this step's scalar inputs into buffer cb
    if (tid < 32){
      int b = tid & 7, wch = tid >> 3;
      long idx = (long)(gb0 + b)*TSTEPS + t;
      char* inp = smem + OFF_INP + cb*128;
      if      (wch == 0) ((int*)inp)[b]        = X[idx];
      else if (wch == 1) ((int*)inp)[8 + b]    = A[idx];
      else if (wch == 2) ((float*)inp)[16 + b] = R[idx];
      else               ((float*)inp)[24 + b] = Dn[idx];
    }

    // ---- recurrent GEMM: W in regs, h via broadcast LDS ----
    {
      const ulonglong2* hp = (const ulonglong2*)(hbuf + cb*(BPC*HID));
      float* part = partS + cb*(8*8*128) + kc*(8*128);
      #pragma unroll 2
      for (int b = 0; b < 8; ++b){
        const ulonglong2* h8 = hp + b*(HID/4) + kc*8;
        ull a0 = 0, a1 = 0;
        #pragma unroll
        for (int j = 0; j < 8; ++j){
          ulonglong2 hv = h8[j];         // single-address broadcast: 1 wavefront
          a0 = fma2(w0[2*j], hv.x, a0);  a0 = fma2(w0[2*j+1], hv.y, a0);
          a1 = fma2(w1[2*j], hv.x, a1);  a1 = fma2(w1[2*j+1], hv.y, a1);
        }
        float2 pr = make_float2(lo32(a0) + hi32(a0), lo32(a1) + hi32(a1));
        *(float2*)(part + b*128 + lr0) = pr;   // conflict-free: lanes consecutive
      }
    }

    __syncthreads();

    // ---- epilogue on threads 0..255 ----
    if (tid < 256){
      const char* inp = smem + OFF_INP + cb*128;
      int   xi = ((const int*)inp)[eb];
      int   ai = ((const int*)inp)[8 + eb];
      float rv = ((const float*)inp)[16 + eb];
      float dv = ((const float*)inp)[24 + eb];
      const float* pG = partS + cb*(8*8*128) + eb*128;

      float gate[4];
      #pragma unroll
      for (int g4 = 0; g4 < 4; ++g4){
        int lr = g4*32 + eu;
        float s = WihT[xi*128 + lr] + WihT[(64+ai)*128 + lr]
                + WihT[80*128 + lr]*rv + WihT[81*128 + lr]*dv + biasS[lr];
        #pragma unroll
        for (int k8 = 0; k8 < 8; ++k8)
          s += pG[k8*(8*128) + lr];
        gate[g4] = s;
      }
      float I = sigf(gate[0]);
      float F = sigf(gate[1]);
      float G = tanhf_(gate[2]);
      float O = sigf(gate[3]);
      c = F*c + I*G;
      float hv = O * tanhf_(c);
      h_last = hv;

      // broadcast h (for step t+1) to all 8 CTAs' buffer nb
      if (t < TSTEPS-1){
        unsigned ho = hoff0 + (unsigned)(nb*(BPC*HID)*4);
        unsigned mo = (unsigned)(OFF_MBAR + nb*8);
        #pragma unroll
        for (int p = 0; p < CLU; ++p)
          st_async_f32(ra[p] + ho, hv, ra[p] + mo);
      }

      // features[b][t][u]
      out[((size_t)gbb*TSTEPS + t)*HID + ug] = hv;
    }
  }

  if (tid < 256){
    size_t fo = (size_t)BATCH*TSTEPS*HID;
    out[fo + (size_t)gbb*(2*HID) + ug]       = h_last;
    out[fo + (size_t)gbb*(2*HID) + HID + ug] = c;
  }

  asm volatile("barrier.cluster.arrive.aligned;" ::: "memory");
  asm volatile("barrier.cluster.wait.aligned;"   ::: "memory");
}

extern "C" void kernel_launch(void* const* d_in, const int* in_sizes, int n_in,
                              void* d_out, int out_size)
{
  const int*   X   = (const int*)  d_in[0];
  const float* H0  = (const float*)d_in[1];
  const int*   A   = (const int*)  d_in[2];
  const float* R   = (const float*)d_in[3];
  const float* Dn  = (const float*)d_in[4];
  const float* Wih = (const float*)d_in[5];
  const float* Whh = (const float*)d_in[6];
  const float* bih = (const float*)d_in[7];
  const float* bhh = (const float*)d_in[8];
  float* out = (float*)d_out;

  cudaFuncSetAttribute(lstm_scan_kernel,
                       cudaFuncAttributeMaxDynamicSharedMemorySize, SMEM_TOTAL);
  lstm_scan_kernel<<<BATCH, NTHR, SMEM_TOTAL>>>(X, H0, A, R, Dn, Wih, Whh, bih, bhh, out);
}